// round 2
// baseline (speedup 1.0000x reference)
#include <cuda_runtime.h>
#include <cuda_bf16.h>
#include <stdint.h>

// Problem constants
#define N_ROWS 16384
#define F_DIM  256
#define K_SEL  8192   // ceil(0.5 * 16384)

// Output layout (flat f32): X_pooled [K_SEL*F_DIM] | A_pooled [K_SEL*K_SEL] | idx [K_SEL]
#define OUT_X_OFF 0
#define OUT_A_OFF (K_SEL * F_DIM)                       // 2,097,152
#define OUT_I_OFF (OUT_A_OFF + (size_t)K_SEL * K_SEL)   // 69,206,016

// Scratch (device globals: no allocations allowed)
__device__ unsigned long long g_keys[N_ROWS];
__device__ int g_rank[N_ROWS];
__device__ int g_idx[K_SEL];

// ---------------------------------------------------------------------------
// Kernel 1: scores = X @ v ; build sortable u64 key; zero rank array.
// One warp per row, lane-strided accumulation (c = lane + 32*t) with EXPLICIT
// rounded mul + rounded add (NO fma) to bit-match XLA's fused mul+row-reduce,
// then xor shuffle tree (bit-identical to shfl-down tree at lane 0).
// key = (~orderedU32(score) << 32) | row  -> ascending key order ==
// descending score, ties broken by ascending row index (lax.top_k semantics).
// ---------------------------------------------------------------------------
__global__ __launch_bounds__(256) void scores_kernel(
    const float* __restrict__ X, const float* __restrict__ sv)
{
    int gwarp = (blockIdx.x * blockDim.x + threadIdx.x) >> 5;
    int lane  = threadIdx.x & 31;
    if (gwarp >= N_ROWS) return;

    const float* xr = X + (size_t)gwarp * F_DIM;
    float acc = 0.0f;
#pragma unroll
    for (int t = 0; t < F_DIM / 32; t++) {
        int c = lane + 32 * t;
        // rounded multiply, rounded add — no contraction into FFMA
        acc = __fadd_rn(acc, __fmul_rn(__ldg(xr + c), __ldg(sv + c)));
    }
#pragma unroll
    for (int o = 16; o > 0; o >>= 1)
        acc = __fadd_rn(acc, __shfl_xor_sync(0xFFFFFFFFu, acc, o));

    if (lane == 0) {
        unsigned ub = __float_as_uint(acc);
        // monotonic ascending mapping of float -> u32
        unsigned u = (ub & 0x80000000u) ? ~ub : (ub | 0x80000000u);
        unsigned long long key =
            ((unsigned long long)(~u) << 32) | (unsigned)gwarp;
        g_keys[gwarp] = key;
        g_rank[gwarp] = 0;
    }
}

// ---------------------------------------------------------------------------
// Kernel 2: exact rank of each key = #{j : key_j < key_i} (keys are unique).
// Grid (64, 16): block.x owns 256 i-keys (one per thread), block.y owns a
// 1024-key j-slice staged in smem (broadcast reads). atomicAdd partial count.
// ---------------------------------------------------------------------------
__global__ __launch_bounds__(256) void rank_kernel()
{
    __shared__ unsigned long long sk[1024];
    int i = blockIdx.x * 256 + threadIdx.x;
    unsigned long long ki = g_keys[i];

    int base = blockIdx.y * 1024;
#pragma unroll
    for (int t = 0; t < 4; t++)
        sk[threadIdx.x + 256 * t] = g_keys[base + threadIdx.x + 256 * t];
    __syncthreads();

    int cnt = 0;
    const ulonglong2* sk2 = (const ulonglong2*)sk;
#pragma unroll 8
    for (int j = 0; j < 512; j++) {
        ulonglong2 k2 = sk2[j];            // LDS.128 broadcast across warp
        cnt += (k2.x < ki);
        cnt += (k2.y < ki);
    }
    atomicAdd(&g_rank[i], cnt);
}

// ---------------------------------------------------------------------------
// Kernel 3: scatter — rank p < K_SEL means row i is the p-th selected row.
// Also emit idx tail of the output (as f32).
// ---------------------------------------------------------------------------
__global__ __launch_bounds__(256) void scatter_kernel(float* __restrict__ out_idx)
{
    int i = blockIdx.x * 256 + threadIdx.x;
    int p = g_rank[i];
    if (p < K_SEL) {
        g_idx[p] = i;
        out_idx[p] = (float)i;
    }
}

// ---------------------------------------------------------------------------
// Kernel 4: X_pooled[p] = X[idx[p]]  (8192 x 256 f32, float4 copies)
// ---------------------------------------------------------------------------
__global__ __launch_bounds__(64) void xgather_kernel(
    const float* __restrict__ X, float* __restrict__ outX)
{
    int p = blockIdx.x;
    int src = g_idx[p];
    const float4* s = (const float4*)(X + (size_t)src * F_DIM);
    float4* d = (float4*)(outX + (size_t)p * F_DIM);
    d[threadIdx.x] = s[threadIdx.x];
}

// ---------------------------------------------------------------------------
// Kernel 5: A_pooled[p][q] = A[idx[p]][idx[q]].
// One block per output row: stage the full 64KB A-row coalesced into smem,
// then gather columns from smem (random LDS) and write STG.128 coalesced.
// idx[] reads are LDG.128, L2-resident (32KB working set).
// ---------------------------------------------------------------------------
__global__ __launch_bounds__(256) void agather_kernel(
    const float* __restrict__ A, float* __restrict__ outA)
{
    extern __shared__ float srow[];  // 16384 floats = 64KB
    int p = blockIdx.x;
    int row = g_idx[p];

    const float4* src = (const float4*)(A + (size_t)row * N_ROWS);
    float4* sr4 = (float4*)srow;
#pragma unroll
    for (int t = 0; t < 16; t++)
        sr4[threadIdx.x + 256 * t] = src[threadIdx.x + 256 * t];
    __syncthreads();

    float4* dst = (float4*)(outA + (size_t)p * K_SEL);
    const int4* idx4 = (const int4*)g_idx;
#pragma unroll
    for (int t = 0; t < 8; t++) {
        int q4 = threadIdx.x + 256 * t;      // quad index, coalesced
        int4 id = __ldg(idx4 + q4);
        float4 v;
        v.x = srow[id.x];
        v.y = srow[id.y];
        v.z = srow[id.z];
        v.w = srow[id.w];
        dst[q4] = v;
    }
}

// ---------------------------------------------------------------------------
extern "C" void kernel_launch(void* const* d_in, const int* in_sizes, int n_in,
                              void* d_out, int out_size)
{
    const float* X  = (const float*)d_in[0];   // [16384, 256]
    const float* A  = (const float*)d_in[1];   // [16384, 16384]
    const float* sv = (const float*)d_in[2];   // [256, 1]
    float* out = (float*)d_out;

    // 64KB dynamic smem for the A-row stage (idempotent; legal during capture)
    cudaFuncSetAttribute(agather_kernel,
                         cudaFuncAttributeMaxDynamicSharedMemorySize, 65536);

    // 1) scores + keys (+ rank zeroing)
    scores_kernel<<<(N_ROWS * 32) / 256, 256>>>(X, sv);

    // 2) exact ranks via full-chip pairwise count
    dim3 rgrid(N_ROWS / 256, 16);
    rank_kernel<<<rgrid, 256>>>();

    // 3) scatter top-K indices (+ idx output)
    scatter_kernel<<<N_ROWS / 256, 256>>>(out + OUT_I_OFF);

    // 4) X gather
    xgather_kernel<<<K_SEL, 64>>>(X, out + OUT_X_OFF);

    // 5) A double-gather (the heavy one)
    agather_kernel<<<K_SEL, 256, 65536>>>(A, out + OUT_A_OFF);
}